// round 6
// baseline (speedup 1.0000x reference)
#include <cuda_runtime.h>
#include <cstdint>

#define S_LEN 2048
#define DM    512
#define NH    8
#define MROWS 8192

// ---- scratch (allocation-free) ----
__device__ float g_X [MROWS * DM];
__device__ float g_Q [MROWS * DM];
__device__ float g_K [MROWS * DM];
__device__ float g_V [MROWS * DM];
__device__ float g_Vt[MROWS * DM];   // [b,h][d][s]
__device__ float g_A [MROWS * DM];
__device__ float g_Wt[4][DM * DM];

// ---- helpers ----
__device__ __forceinline__ uint32_t smem_u32(const void* p) {
    uint32_t a;
    asm("{ .reg .u64 t; cvta.to.shared.u64 t, %1; cvt.u32.u64 %0, t; }"
        : "=r"(a) : "l"(p));
    return a;
}
__device__ __forceinline__ uint32_t tf32r(float f) {
    uint32_t u;
    asm("cvt.rna.tf32.f32 %0, %1;" : "=r"(u) : "f"(f));
    return u;
}
__device__ __forceinline__ void cpa16(uint32_t s, const void* g) {
    asm volatile("cp.async.cg.shared.global [%0], [%1], 16;" :: "r"(s), "l"(g) : "memory");
}
#define CP_COMMIT() asm volatile("cp.async.commit_group;" ::: "memory")
#define CP_WAIT0()  asm volatile("cp.async.wait_group 0;" ::: "memory")
#define CP_WAIT1()  asm volatile("cp.async.wait_group 1;" ::: "memory")

__device__ __forceinline__ void mma8(float* c,
    uint32_t a0, uint32_t a1, uint32_t a2, uint32_t a3,
    uint32_t b0, uint32_t b1)
{
    asm volatile(
        "mma.sync.aligned.m16n8k8.row.col.f32.tf32.tf32.f32 "
        "{%0,%1,%2,%3}, {%4,%5,%6,%7}, {%8,%9}, {%0,%1,%2,%3};"
        : "+f"(c[0]), "+f"(c[1]), "+f"(c[2]), "+f"(c[3])
        : "r"(a0), "r"(a1), "r"(a2), "r"(a3), "r"(b0), "r"(b1));
}

// ===========================================================================
// tf32 GEMM, fused multi-weight: which = blockIdx.x>>1 selects (Bt,bias,C).
// CTA 128(M)x256(N), BK=32, 3-stage cp.async, 8 warps, warp tile 64x64.
// smem floats: A[3][4096]@0, B[3][8192]@12288 -> 36864 floats = 147456 B.
// ===========================================================================
__global__ __launch_bounds__(256, 1) void gemm_mma(
    const float* __restrict__ A, const float* __restrict__ BtBase,
    const float* __restrict__ b0, const float* __restrict__ b1,
    const float* __restrict__ b2,
    float* __restrict__ C0, float* __restrict__ C1, float* __restrict__ C2,
    int cvt_out)
{
    extern __shared__ __align__(16) float smf[];
    const uint32_t sbu = smem_u32(smf);
    const int tid = threadIdx.x, w = tid >> 5, lane = tid & 31;
    const int grp = lane >> 2, tig = lane & 3;
    const int g4 = grp * 4;
    const int wm = (w & 1) * 64, wn = (w >> 1) * 64;
    const int which = blockIdx.x >> 1;
    const int bn = (blockIdx.x & 1) << 8;
    const int bm = blockIdx.y << 7;

    const float* Bt = BtBase + (size_t)which * DM * DM;
    const float* bias = (which == 0) ? b0 : (which == 1) ? b1 : b2;
    float* C = (which == 0) ? C0 : (which == 1) ? C1 : C2;

    const float* Ab = A + (size_t)bm * 512;
    const float* Bb = Bt + (size_t)bn * 512;

    float acc[4][8][4] = {};

    auto ld_stage = [&](int kc) {
        int st = kc % 3;
        uint32_t aB = sbu + (uint32_t)(st * 4096) * 4u;
        uint32_t bB = sbu + (uint32_t)(12288 + st * 8192) * 4u;
        const float* ga = Ab + kc * 32;
        const float* gb = Bb + kc * 32;
        #pragma unroll
        for (int i = 0; i < 4; i++) {
            int idx = tid + i * 256;
            int r = idx >> 3, c4 = idx & 7;
            cpa16(aB + (uint32_t)(r * 32 + 4 * (c4 ^ (r & 7))) * 4u,
                  ga + (size_t)r * 512 + c4 * 4);
        }
        #pragma unroll
        for (int i = 0; i < 8; i++) {
            int idx = tid + i * 256;
            int r = idx >> 3, c4 = idx & 7;
            cpa16(bB + (uint32_t)(r * 32 + 4 * (c4 ^ (r & 7))) * 4u,
                  gb + (size_t)r * 512 + c4 * 4);
        }
    };

    ld_stage(0); CP_COMMIT();
    ld_stage(1); CP_COMMIT();

    for (int kc = 0; kc < 16; kc++) {
        if (kc < 14) CP_WAIT1(); else CP_WAIT0();
        __syncthreads();
        if (kc + 2 < 16) { ld_stage(kc + 2); CP_COMMIT(); }
        const float* pA = smf + (kc % 3) * 4096;
        const float* pB = smf + 12288 + (kc % 3) * 8192;

        #pragma unroll
        for (int ks = 0; ks < 4; ks++) {
            int kk = ks * 8 + tig;
            int k0 = kk ^ g4, k1 = (kk + 4) ^ g4;
            uint32_t a[4][4], bfr[8][2];
            #pragma unroll
            for (int mt = 0; mt < 4; mt++) {
                int r = wm + mt * 16 + grp;
                a[mt][0] = __float_as_uint(pA[r * 32 + k0]);
                a[mt][1] = __float_as_uint(pA[(r + 8) * 32 + k0]);
                a[mt][2] = __float_as_uint(pA[r * 32 + k1]);
                a[mt][3] = __float_as_uint(pA[(r + 8) * 32 + k1]);
            }
            #pragma unroll
            for (int nt = 0; nt < 8; nt++) {
                int n = wn + nt * 8 + grp;
                bfr[nt][0] = __float_as_uint(pB[n * 32 + k0]);
                bfr[nt][1] = __float_as_uint(pB[n * 32 + k1]);
            }
            #pragma unroll
            for (int mt = 0; mt < 4; mt++)
                #pragma unroll
                for (int nt = 0; nt < 8; nt++)
                    mma8(acc[mt][nt], a[mt][0], a[mt][1], a[mt][2], a[mt][3],
                         bfr[nt][0], bfr[nt][1]);
        }
    }

    float bb0[8], bb1[8];
    #pragma unroll
    for (int nt = 0; nt < 8; nt++) {
        int c = bn + wn + nt * 8 + 2 * tig;
        bb0[nt] = bias[c]; bb1[nt] = bias[c + 1];
    }
    #pragma unroll
    for (int mt = 0; mt < 4; mt++) {
        int r0 = bm + wm + mt * 16 + grp;
        #pragma unroll
        for (int nt = 0; nt < 8; nt++) {
            int c = bn + wn + nt * 8 + 2 * tig;
            float v00 = acc[mt][nt][0] + bb0[nt], v01 = acc[mt][nt][1] + bb1[nt];
            float v10 = acc[mt][nt][2] + bb0[nt], v11 = acc[mt][nt][3] + bb1[nt];
            if (cvt_out) {
                *(uint2*)(C + (size_t)r0 * 512 + c) = make_uint2(tf32r(v00), tf32r(v01));
                *(uint2*)(C + (size_t)(r0 + 8) * 512 + c) = make_uint2(tf32r(v10), tf32r(v11));
            } else {
                *(float2*)(C + (size_t)r0 * 512 + c) = make_float2(v00, v01);
                *(float2*)(C + (size_t)(r0 + 8) * 512 + c) = make_float2(v10, v11);
            }
        }
    }
}

// ===========================================================================
// Flash attention (mma.sync tf32). Grid (16, 32), 256 threads, 8 warps.
// Warp roles: rm = w&3 (32-row group), cs = w>>2 (64-col slice).
// S warp tile 32x64; exp+P stay warp-private; PV uses ONLY own P block
// (k-slice = own 64 cols) -> no CTA sync between exp and PV.
// 2-way O partials reduced in epilogue.
// smem floats: Q@0(8192) K@8192(2x8192) V@24576(2x8192)
//              P@40960(8x2048) sL@57344(256) -> 57600 fl = 230400 B
// ===========================================================================
__device__ __forceinline__ void attn_ld_k(uint32_t sbu, const float* Kb, int j, int tid) {
    uint32_t base = sbu + (uint32_t)(8192 + (j & 1) * 8192) * 4u;
    const float* g = Kb + (size_t)j * 128 * 512;
    #pragma unroll
    for (int i = 0; i < 8; i++) {
        int idx = tid + i * 256;
        int r = idx >> 4, c4 = idx & 15;
        cpa16(base + (uint32_t)(r * 64 + 4 * (c4 ^ (r & 7))) * 4u,
              g + (size_t)r * 512 + c4 * 4);
    }
}
__device__ __forceinline__ void attn_ld_v(uint32_t sbu, const float* Vb, int j, int tid) {
    uint32_t base = sbu + (uint32_t)(24576 + (j & 1) * 8192) * 4u;
    const float* g = Vb + j * 128;
    #pragma unroll
    for (int i = 0; i < 8; i++) {
        int idx = tid + i * 256;
        int d = idx >> 5, c4 = idx & 31;
        cpa16(base + (uint32_t)(d * 128 + 4 * (c4 ^ (d & 7))) * 4u,
              g + (size_t)d * 2048 + c4 * 4);
    }
}

__global__ __launch_bounds__(256, 1) void attn_mma(
    const float* __restrict__ Q, const float* __restrict__ K,
    const float* __restrict__ Vt, float* __restrict__ O)
{
    extern __shared__ __align__(16) float smf[];
    const uint32_t sbu = smem_u32(smf);
    const int tid = threadIdx.x, w = tid >> 5, lane = tid & 31;
    const int grp = lane >> 2, tig = lane & 3;
    const int g4 = grp * 4;
    const int rm = w & 3, cs = w >> 2;
    const int bh = blockIdx.y, b = bh >> 3, hh = bh & 7;
    const int q0 = blockIdx.x << 7;

    const float* Qb = Q + ((size_t)b * S_LEN + q0) * DM + hh * 64;
    const float* Kb = K + ((size_t)b * S_LEN) * DM + hh * 64;
    const float* Vb = Vt + (size_t)bh * 64 * S_LEN;

    // prologue: Q + KV(0) in group0, KV(1) in group1
    #pragma unroll
    for (int i = 0; i < 8; i++) {
        int idx = tid + i * 256;
        int r = idx >> 4, c4 = idx & 15;
        cpa16(sbu + (uint32_t)(r * 64 + 4 * (c4 ^ (r & 7))) * 4u,
              Qb + (size_t)r * 512 + c4 * 4);
    }
    attn_ld_k(sbu, Kb, 0, tid); attn_ld_v(sbu, Vb, 0, tid); CP_COMMIT();
    attn_ld_k(sbu, Kb, 1, tid); attn_ld_v(sbu, Vb, 1, tid); CP_COMMIT();

    const float* sQ = smf;
    float* sP = smf + 40960 + w * 2048;   // own 32x64 block
    float* sL = smf + 57344;

    float o[2][8][4] = {};
    float l[4] = {};

    for (int j = 0; j < 16; j++) {
        if (j < 14) CP_WAIT1(); else CP_WAIT0();
        __syncthreads();
        const float* sK = smf + 8192 + (j & 1) * 8192;
        const float* sV = smf + 24576 + (j & 1) * 8192;

        // ---- S = Q @ K^T : warp tile rows [rm*32,+32), cols [cs*64,+64) ----
        float s[2][8][4] = {};
        #pragma unroll
        for (int ks = 0; ks < 8; ks++) {
            int kk = ks * 8 + tig;
            int k0 = kk ^ g4, k1 = (kk + 4) ^ g4;
            uint32_t a[2][4], bfr[8][2];
            #pragma unroll
            for (int mt = 0; mt < 2; mt++) {
                int r = rm * 32 + mt * 16 + grp;
                a[mt][0] = __float_as_uint(sQ[r * 64 + k0]);
                a[mt][1] = __float_as_uint(sQ[(r + 8) * 64 + k0]);
                a[mt][2] = __float_as_uint(sQ[r * 64 + k1]);
                a[mt][3] = __float_as_uint(sQ[(r + 8) * 64 + k1]);
            }
            #pragma unroll
            for (int nt = 0; nt < 8; nt++) {
                int n = cs * 64 + nt * 8 + grp;
                bfr[nt][0] = __float_as_uint(sK[n * 64 + k0]);
                bfr[nt][1] = __float_as_uint(sK[n * 64 + k1]);
            }
            #pragma unroll
            for (int mt = 0; mt < 2; mt++)
                #pragma unroll
                for (int nt = 0; nt < 8; nt++)
                    mma8(s[mt][nt], a[mt][0], a[mt][1], a[mt][2], a[mt][3],
                         bfr[nt][0], bfr[nt][1]);
        }

        // ---- exp + row-sums + P write (warp-private, swizzled) ----
        #pragma unroll
        for (int mt = 0; mt < 2; mt++) {
            int lr = mt * 16 + grp;
            int sx = 4 * grp;
            #pragma unroll
            for (int nt = 0; nt < 8; nt++) {
                float e0 = __expf(s[mt][nt][0] * 0.125f);
                float e1 = __expf(s[mt][nt][1] * 0.125f);
                float e2 = __expf(s[mt][nt][2] * 0.125f);
                float e3 = __expf(s[mt][nt][3] * 0.125f);
                l[mt * 2] += e0 + e1;
                l[mt * 2 + 1] += e2 + e3;
                int c = (nt * 8 + 2 * tig) ^ sx;
                *(uint2*)&sP[lr * 64 + c] = make_uint2(tf32r(e0), tf32r(e1));
                *(uint2*)&sP[(lr + 8) * 64 + c] = make_uint2(tf32r(e2), tf32r(e3));
            }
        }
        __syncwarp();

        // ---- O_partial += P_own @ V[k-slice = own cols] ----
        #pragma unroll
        for (int ks = 0; ks < 8; ks++) {
            int kk = ks * 8 + tig;
            int k0 = kk ^ g4, k1 = (kk + 4) ^ g4;
            int jg0 = (cs * 64 + kk) ^ g4, jg1 = (cs * 64 + kk + 4) ^ g4;
            uint32_t a[2][4], bfr[8][2];
            #pragma unroll
            for (int mt = 0; mt < 2; mt++) {
                int lr = mt * 16 + grp;
                a[mt][0] = __float_as_uint(sP[lr * 64 + k0]);
                a[mt][1] = __float_as_uint(sP[(lr + 8) * 64 + k0]);
                a[mt][2] = __float_as_uint(sP[lr * 64 + k1]);
                a[mt][3] = __float_as_uint(sP[(lr + 8) * 64 + k1]);
            }
            #pragma unroll
            for (int nt = 0; nt < 8; nt++) {
                int d = nt * 8 + grp;
                bfr[nt][0] = __float_as_uint(sV[d * 128 + jg0]);
                bfr[nt][1] = __float_as_uint(sV[d * 128 + jg1]);
            }
            #pragma unroll
            for (int mt = 0; mt < 2; mt++)
                #pragma unroll
                for (int nt = 0; nt < 8; nt++)
                    mma8(o[mt][nt], a[mt][0], a[mt][1], a[mt][2], a[mt][3],
                         bfr[nt][0], bfr[nt][1]);
        }
        __syncthreads();   // all warps done reading K/V buffer (j&1)
        if (j + 2 < 16) {
            attn_ld_k(sbu, Kb, j + 2, tid);
            attn_ld_v(sbu, Vb, j + 2, tid);
            CP_COMMIT();
        }
    }

    // ---- epilogue ----
    // row-sum partials: quad reduce, write sL[cs][row]
    #pragma unroll
    for (int slot = 0; slot < 4; slot++) {
        float v = l[slot];
        v += __shfl_xor_sync(0xffffffffu, v, 1);
        v += __shfl_xor_sync(0xffffffffu, v, 2);
        if (tig == 0) {
            int row = rm * 32 + (slot >> 1) * 16 + grp + (slot & 1) * 8;
            sL[cs * 128 + row] = v;
        }
    }
    // cs==1 warps stage O partials in K region (plain layout, per rm block)
    float* stg = smf + 8192 + rm * 2048;
    if (cs == 1) {
        #pragma unroll
        for (int mt = 0; mt < 2; mt++) {
            int lr = mt * 16 + grp;
            #pragma unroll
            for (int nt = 0; nt < 8; nt++) {
                int c = nt * 8 + 2 * tig;
                *(float2*)&stg[lr * 64 + c] = make_float2(o[mt][nt][0], o[mt][nt][1]);
                *(float2*)&stg[(lr + 8) * 64 + c] = make_float2(o[mt][nt][2], o[mt][nt][3]);
            }
        }
    }
    __syncthreads();
    if (cs == 0) {
        #pragma unroll
        for (int mt = 0; mt < 2; mt++) {
            int lr = mt * 16 + grp;
            int r0 = rm * 32 + lr, r1 = r0 + 8;
            float inv0 = 1.f / (sL[r0] + sL[128 + r0]);
            float inv1 = 1.f / (sL[r1] + sL[128 + r1]);
            float* op0 = O + ((size_t)b * S_LEN + q0 + r0) * DM + hh * 64;
            float* op1 = O + ((size_t)b * S_LEN + q0 + r1) * DM + hh * 64;
            #pragma unroll
            for (int nt = 0; nt < 8; nt++) {
                int c = nt * 8 + 2 * tig;
                float2 p0 = *(float2*)&stg[lr * 64 + c];
                float2 p1 = *(float2*)&stg[(lr + 8) * 64 + c];
                *(uint2*)(op0 + c) = make_uint2(
                    tf32r((o[mt][nt][0] + p0.x) * inv0),
                    tf32r((o[mt][nt][1] + p0.y) * inv0));
                *(uint2*)(op1 + c) = make_uint2(
                    tf32r((o[mt][nt][2] + p1.x) * inv1),
                    tf32r((o[mt][nt][3] + p1.y) * inv1));
            }
        }
    }
}

// ===========================================================================
// prep kernels
// ===========================================================================
__global__ void cvt_x(const float4* __restrict__ src, float4* __restrict__ dst) {
    int i = blockIdx.x * 256 + threadIdx.x;
    float4 v = src[i];
    uint4 u = make_uint4(tf32r(v.x), tf32r(v.y), tf32r(v.z), tf32r(v.w));
    dst[i] = *(float4*)&u;
}

__global__ void transposeW(const float* __restrict__ s0, const float* __restrict__ s1,
                           const float* __restrict__ s2, const float* __restrict__ s3,
                           float* __restrict__ dstAll) {
    __shared__ float t[32][33];
    const float* src = (blockIdx.z == 0) ? s0 : (blockIdx.z == 1) ? s1
                     : (blockIdx.z == 2) ? s2 : s3;
    float* dst = dstAll + (size_t)blockIdx.z * DM * DM;
    int x0 = blockIdx.x * 32, y0 = blockIdx.y * 32;
    int tx = threadIdx.x, ty = threadIdx.y;
    #pragma unroll
    for (int i = 0; i < 4; i++)
        t[ty + i * 8][tx] = src[(size_t)(y0 + ty + i * 8) * 512 + x0 + tx];
    __syncthreads();
    #pragma unroll
    for (int i = 0; i < 4; i++)
        dst[(size_t)(x0 + ty + i * 8) * 512 + y0 + tx] =
            __uint_as_float(tf32r(t[tx][ty + i * 8]));
}

__global__ void transpose_v(const float* __restrict__ V, float* __restrict__ Vt) {
    __shared__ float t[32][33];
    int bh = blockIdx.z, b = bh >> 3, h = bh & 7;
    int s0 = blockIdx.x * 32, d0 = blockIdx.y * 32;
    int tx = threadIdx.x, ty = threadIdx.y;
    #pragma unroll
    for (int i = 0; i < 4; i++)
        t[ty + i * 8][tx] =
            V[((size_t)b * S_LEN + s0 + ty + i * 8) * DM + h * 64 + d0 + tx];
    __syncthreads();
    #pragma unroll
    for (int i = 0; i < 4; i++)
        Vt[((size_t)bh * 64 + d0 + ty + i * 8) * S_LEN + s0 + tx] = t[tx][ty + i * 8];
}

// ===========================================================================
extern "C" void kernel_launch(void* const* d_in, const int* in_sizes, int n_in,
                              void* d_out, int out_size)
{
    const float* x  = (const float*)d_in[0];
    const float* Wq = (const float*)d_in[1];
    const float* bq = (const float*)d_in[2];
    const float* Wk = (const float*)d_in[3];
    const float* bk = (const float*)d_in[4];
    const float* Wv = (const float*)d_in[5];
    const float* bv = (const float*)d_in[6];
    const float* Wh = (const float*)d_in[7];
    const float* bh = (const float*)d_in[8];
    float* out = (float*)d_out;

    float *Xp, *Qp, *Kp, *Vp, *Vtp, *Ap, *Wtp;
    cudaGetSymbolAddress((void**)&Xp, g_X);
    cudaGetSymbolAddress((void**)&Qp, g_Q);
    cudaGetSymbolAddress((void**)&Kp, g_K);
    cudaGetSymbolAddress((void**)&Vp, g_V);
    cudaGetSymbolAddress((void**)&Vtp, g_Vt);
    cudaGetSymbolAddress((void**)&Ap, g_A);
    cudaGetSymbolAddress((void**)&Wtp, g_Wt);

    const int GEMM_SMEM = 36864 * 4;   // 147456
    const int ATTN_SMEM = 57600 * 4;   // 230400
    cudaFuncSetAttribute(gemm_mma, cudaFuncAttributeMaxDynamicSharedMemorySize, GEMM_SMEM);
    cudaFuncSetAttribute(attn_mma, cudaFuncAttributeMaxDynamicSharedMemorySize, ATTN_SMEM);

    cvt_x<<<MROWS * DM / 4 / 256, 256>>>((const float4*)x, (float4*)Xp);

    dim3 tb(32, 8);
    transposeW<<<dim3(16, 16, 4), tb>>>(Wq, Wk, Wv, Wh, Wtp);

    // fused QKV: which = blockIdx.x>>1 in {0,1,2}
    gemm_mma<<<dim3(6, 64), 256, GEMM_SMEM>>>(Xp, Wtp, bq, bk, bv, Qp, Kp, Vp, 1);

    transpose_v<<<dim3(64, 2, 32), tb>>>(Vp, Vtp);

    attn_mma<<<dim3(16, 32), 256, ATTN_SMEM>>>(Qp, Kp, Vtp, Ap);

    // Wh: grid.x = 2 -> which always 0
    gemm_mma<<<dim3(2, 64), 256, GEMM_SMEM>>>(Ap, Wtp + 3 * DM * DM,
                                              bh, bh, bh, out, out, out, 0);
}

// round 9
// speedup vs baseline: 1.7184x; 1.7184x over previous
#include <cuda_runtime.h>
#include <cuda_fp16.h>
#include <cstdint>

#define S_LEN 2048
#define DM    512
#define MROWS 8192

// ---- scratch (allocation-free) ----
__device__ __half g_Xh[MROWS * DM];
__device__ __half g_Q [MROWS * DM];
__device__ __half g_K [MROWS * DM];
__device__ __half g_V [MROWS * DM];
__device__ __half g_Vt[MROWS * DM];   // [b,h][d][s]
__device__ __half g_A [MROWS * DM];
__device__ __half g_Wt[4][DM * DM];   // [n][k] transposed, fp16

// ---- helpers ----
__device__ __forceinline__ uint32_t smem_u32(const void* p) {
    uint32_t a;
    asm("{ .reg .u64 t; cvta.to.shared.u64 t, %1; cvt.u32.u64 %0, t; }"
        : "=r"(a) : "l"(p));
    return a;
}
__device__ __forceinline__ void cpa16(uint32_t s, const void* g) {
    asm volatile("cp.async.cg.shared.global [%0], [%1], 16;" :: "r"(s), "l"(g) : "memory");
}
#define CP_COMMIT() asm volatile("cp.async.commit_group;" ::: "memory")
#define CP_WAIT0()  asm volatile("cp.async.wait_group 0;" ::: "memory")
#define CP_WAIT1()  asm volatile("cp.async.wait_group 1;" ::: "memory")

__device__ __forceinline__ void mma16(float* c,
    uint32_t a0, uint32_t a1, uint32_t a2, uint32_t a3,
    uint32_t b0, uint32_t b1)
{
    asm volatile(
        "mma.sync.aligned.m16n8k16.row.col.f32.f16.f16.f32 "
        "{%0,%1,%2,%3}, {%4,%5,%6,%7}, {%8,%9}, {%0,%1,%2,%3};"
        : "+f"(c[0]), "+f"(c[1]), "+f"(c[2]), "+f"(c[3])
        : "r"(a0), "r"(a1), "r"(a2), "r"(a3), "r"(b0), "r"(b1));
}
__device__ __forceinline__ uint32_t h2u(__half2 h) {
    return *reinterpret_cast<uint32_t*>(&h);
}
__device__ __forceinline__ uint32_t lds32(const __half* p) {
    return *reinterpret_cast<const uint32_t*>(p);
}

// ===========================================================================
// fp16 GEMM: C[8192,512] = A[8192,512] @ Bt[512,512]^T + bias  (Bt is [n][k])
// CTA 128(M)x256(N), BK=32, 2-stage cp.async, 8 warps, warp tile 64x64.
// smem halves, rows padded to 40 (80B): A[2][128*40]@0, B[2][256*40]@10240.
// Total 61440 B.
// ===========================================================================
__global__ __launch_bounds__(256, 1) void gemm_mma(
    const __half* __restrict__ A, const __half* __restrict__ Bt,
    const float* __restrict__ bias, void* __restrict__ Cout, int half_out)
{
    extern __shared__ __align__(16) __half smh[];
    const uint32_t sbu = smem_u32(smh);
    const int tid = threadIdx.x, w = tid >> 5, lane = tid & 31;
    const int grp = lane >> 2, tig = lane & 3;
    const int wm = (w & 1) * 64, wn = (w >> 1) * 64;
    const int bm = blockIdx.y << 7, bn = blockIdx.x << 8;

    const __half* Ab = A + (size_t)bm * 512;
    const __half* Bb = Bt + (size_t)bn * 512;

    float acc[4][8][4] = {};

    auto ld_stage = [&](int kc) {
        int st = kc & 1;
        uint32_t aB = sbu + (uint32_t)st * 10240u;
        uint32_t bB = sbu + 20480u + (uint32_t)st * 20480u;
        #pragma unroll
        for (int i = 0; i < 2; i++) {
            int idx = tid + i * 256;
            int r = idx >> 2, c = idx & 3;
            cpa16(aB + (uint32_t)(r * 80 + c * 16),
                  Ab + (size_t)r * 512 + kc * 32 + c * 8);
        }
        #pragma unroll
        for (int i = 0; i < 4; i++) {
            int idx = tid + i * 256;
            int r = idx >> 2, c = idx & 3;
            cpa16(bB + (uint32_t)(r * 80 + c * 16),
                  Bb + (size_t)r * 512 + kc * 32 + c * 8);
        }
    };

    ld_stage(0); CP_COMMIT();

    for (int kc = 0; kc < 16; kc++) {
        CP_WAIT0();
        __syncthreads();
        if (kc + 1 < 16) { ld_stage(kc + 1); CP_COMMIT(); }
        const __half* pA = smh + (kc & 1) * 5120;
        const __half* pB = smh + 10240 + (kc & 1) * 10240;

        #pragma unroll
        for (int ks = 0; ks < 2; ks++) {
            uint32_t a[4][4], bfr[8][2];
            #pragma unroll
            for (int mt = 0; mt < 4; mt++) {
                int r = wm + mt * 16 + grp;
                const __half* p = pA + r * 40 + ks * 16 + 2 * tig;
                a[mt][0] = lds32(p);
                a[mt][1] = lds32(p + 8 * 40);
                a[mt][2] = lds32(p + 8);
                a[mt][3] = lds32(p + 8 * 40 + 8);
            }
            #pragma unroll
            for (int nt = 0; nt < 8; nt++) {
                int n = wn + nt * 8 + grp;
                const __half* p = pB + n * 40 + ks * 16 + 2 * tig;
                bfr[nt][0] = lds32(p);
                bfr[nt][1] = lds32(p + 8);
            }
            #pragma unroll
            for (int mt = 0; mt < 4; mt++)
                #pragma unroll
                for (int nt = 0; nt < 8; nt++)
                    mma16(acc[mt][nt], a[mt][0], a[mt][1], a[mt][2], a[mt][3],
                          bfr[nt][0], bfr[nt][1]);
        }
        __syncthreads();
    }

    float bb0[8], bb1[8];
    #pragma unroll
    for (int nt = 0; nt < 8; nt++) {
        int c = bn + wn + nt * 8 + 2 * tig;
        bb0[nt] = bias[c]; bb1[nt] = bias[c + 1];
    }
    #pragma unroll
    for (int mt = 0; mt < 4; mt++) {
        int r0 = bm + wm + mt * 16 + grp;
        #pragma unroll
        for (int nt = 0; nt < 8; nt++) {
            int c = bn + wn + nt * 8 + 2 * tig;
            float v00 = acc[mt][nt][0] + bb0[nt], v01 = acc[mt][nt][1] + bb1[nt];
            float v10 = acc[mt][nt][2] + bb0[nt], v11 = acc[mt][nt][3] + bb1[nt];
            if (half_out) {
                __half* C = (__half*)Cout;
                *(__half2*)(C + (size_t)r0 * 512 + c) = __floats2half2_rn(v00, v01);
                *(__half2*)(C + (size_t)(r0 + 8) * 512 + c) = __floats2half2_rn(v10, v11);
            } else {
                float* C = (float*)Cout;
                *(float2*)(C + (size_t)r0 * 512 + c) = make_float2(v00, v01);
                *(float2*)(C + (size_t)(r0 + 8) * 512 + c) = make_float2(v10, v11);
            }
        }
    }
}

// ===========================================================================
// Flash attention, fp16 mma, register-resident P. Grid (16,32), 256 thr.
// Warp roles: rm = w&3 (32 q-rows), cs = w>>2 (64 score-cols slice).
// QK warp tile 32x64 -> exp -> pack to A-fragments in regs -> PV over own
// 64-col k-slice. 3-buffered K/V, ONE __syncthreads per key tile.
// smem bytes: Q@0(18432) K[3]@18432(3*18432) V[3]@73728(3*17408)
//             sL@125952(1024) -> 126976 B. Rows: Q/K pad 72 h, V pad 136 h.
// ===========================================================================
__global__ __launch_bounds__(256, 1) void attn_mma(
    const __half* __restrict__ Q, const __half* __restrict__ K,
    const __half* __restrict__ Vt, __half* __restrict__ O)
{
    extern __shared__ __align__(16) __half smh[];
    const uint32_t sbu = smem_u32(smh);
    const int tid = threadIdx.x, w = tid >> 5, lane = tid & 31;
    const int grp = lane >> 2, tig = lane & 3;
    const int rm = w & 3, cs = w >> 2;
    const int bh = blockIdx.y, b = bh >> 3, hh = bh & 7;
    const int q0 = blockIdx.x << 7;

    const __half* Qb = Q + ((size_t)b * S_LEN + q0) * DM + hh * 64;
    const __half* Kb = K + ((size_t)b * S_LEN) * DM + hh * 64;
    const __half* Vb = Vt + (size_t)bh * 64 * S_LEN;

    auto ld_k = [&](int j) {
        uint32_t base = sbu + 18432u + (uint32_t)(j % 3) * 18432u;
        const __half* g = Kb + (size_t)j * 128 * 512;
        #pragma unroll
        for (int i = 0; i < 4; i++) {
            int idx = tid + i * 256;
            int r = idx >> 3, c = idx & 7;
            cpa16(base + (uint32_t)(r * 144 + c * 16), g + (size_t)r * 512 + c * 8);
        }
    };
    auto ld_v = [&](int j) {
        uint32_t base = sbu + 73728u + (uint32_t)(j % 3) * 17408u;
        const __half* g = Vb + j * 128;
        #pragma unroll
        for (int i = 0; i < 4; i++) {
            int idx = tid + i * 256;
            int d = idx >> 4, c = idx & 15;
            cpa16(base + (uint32_t)(d * 272 + c * 16), g + (size_t)d * 2048 + c * 8);
        }
    };

    // prologue: Q + (K0,V0), (K1,V1)
    #pragma unroll
    for (int i = 0; i < 4; i++) {
        int idx = tid + i * 256;
        int r = idx >> 3, c = idx & 7;
        cpa16(sbu + (uint32_t)(r * 144 + c * 16), Qb + (size_t)r * 512 + c * 8);
    }
    ld_k(0); ld_v(0); CP_COMMIT();
    ld_k(1); ld_v(1); CP_COMMIT();

    float o[2][8][4] = {};
    float l[4] = {};

    for (int j = 0; j < 16; j++) {
        if (j < 15) CP_WAIT1(); else CP_WAIT0();
        __syncthreads();
        if (j + 2 < 16) { ld_k(j + 2); ld_v(j + 2); CP_COMMIT(); }

        const __half* pQ = smh;
        const __half* pK = smh + 9216 + (j % 3) * 9216;
        const __half* pV = smh + 36864 + (j % 3) * 8704;

        // ---- S = Q @ K^T : rows [rm*32,+32), cols [cs*64,+64) ----
        float s[2][8][4] = {};
        #pragma unroll
        for (int ks = 0; ks < 4; ks++) {
            uint32_t a[2][4], bfr[8][2];
            #pragma unroll
            for (int mt = 0; mt < 2; mt++) {
                int r = rm * 32 + mt * 16 + grp;
                const __half* p = pQ + r * 72 + ks * 16 + 2 * tig;
                a[mt][0] = lds32(p);
                a[mt][1] = lds32(p + 8 * 72);
                a[mt][2] = lds32(p + 8);
                a[mt][3] = lds32(p + 8 * 72 + 8);
            }
            #pragma unroll
            for (int nt = 0; nt < 8; nt++) {
                int n = cs * 64 + nt * 8 + grp;
                const __half* p = pK + n * 72 + ks * 16 + 2 * tig;
                bfr[nt][0] = lds32(p);
                bfr[nt][1] = lds32(p + 8);
            }
            #pragma unroll
            for (int mt = 0; mt < 2; mt++)
                #pragma unroll
                for (int nt = 0; nt < 8; nt++)
                    mma16(s[mt][nt], a[mt][0], a[mt][1], a[mt][2], a[mt][3],
                          bfr[nt][0], bfr[nt][1]);
        }

        // ---- exp + row sums + pack P into A-fragments (registers) ----
        uint32_t pa[2][4][4];
        #pragma unroll
        for (int mt = 0; mt < 2; mt++) {
            #pragma unroll
            for (int nt2 = 0; nt2 < 4; nt2++) {
                float e0 = __expf(s[mt][2*nt2][0] * 0.125f);
                float e1 = __expf(s[mt][2*nt2][1] * 0.125f);
                float e2 = __expf(s[mt][2*nt2][2] * 0.125f);
                float e3 = __expf(s[mt][2*nt2][3] * 0.125f);
                float f0 = __expf(s[mt][2*nt2+1][0] * 0.125f);
                float f1 = __expf(s[mt][2*nt2+1][1] * 0.125f);
                float f2 = __expf(s[mt][2*nt2+1][2] * 0.125f);
                float f3 = __expf(s[mt][2*nt2+1][3] * 0.125f);
                l[mt*2]   += e0 + e1 + f0 + f1;
                l[mt*2+1] += e2 + e3 + f2 + f3;
                pa[mt][nt2][0] = h2u(__floats2half2_rn(e0, e1));
                pa[mt][nt2][1] = h2u(__floats2half2_rn(e2, e3));
                pa[mt][nt2][2] = h2u(__floats2half2_rn(f0, f1));
                pa[mt][nt2][3] = h2u(__floats2half2_rn(f2, f3));
            }
        }

        // ---- O_partial += P_own @ V[own k-slice] ----
        #pragma unroll
        for (int nt2 = 0; nt2 < 4; nt2++) {
            uint32_t bv[8][2];
            #pragma unroll
            for (int dn = 0; dn < 8; dn++) {
                const __half* p = pV + (dn * 8 + grp) * 136 + cs * 64 + nt2 * 16 + 2 * tig;
                bv[dn][0] = lds32(p);
                bv[dn][1] = lds32(p + 8);
            }
            #pragma unroll
            for (int mt = 0; mt < 2; mt++)
                #pragma unroll
                for (int dn = 0; dn < 8; dn++)
                    mma16(o[mt][dn], pa[mt][nt2][0], pa[mt][nt2][1],
                          pa[mt][nt2][2], pa[mt][nt2][3], bv[dn][0], bv[dn][1]);
        }
    }

    __syncthreads();   // all tile reads done before epilogue reuses smem

    float* sL = (float*)((char*)smh + 125952);
    float* stg = (float*)((char*)smh + 18432);   // K region, 32KB used

    // row-sum partials: quad reduce, sL[cs][row]
    #pragma unroll
    for (int slot = 0; slot < 4; slot++) {
        float v = l[slot];
        v += __shfl_xor_sync(0xffffffffu, v, 1);
        v += __shfl_xor_sync(0xffffffffu, v, 2);
        if (tig == 0) {
            int row = rm * 32 + (slot >> 1) * 16 + grp + (slot & 1) * 8;
            sL[cs * 128 + row] = v;
        }
    }
    // cs==1 warps stage O partials (f32)
    if (cs == 1) {
        #pragma unroll
        for (int mt = 0; mt < 2; mt++) {
            int r = rm * 32 + mt * 16 + grp;
            #pragma unroll
            for (int dn = 0; dn < 8; dn++) {
                int c = dn * 8 + 2 * tig;
                *(float2*)&stg[r * 64 + c] = make_float2(o[mt][dn][0], o[mt][dn][1]);
                *(float2*)&stg[(r + 8) * 64 + c] = make_float2(o[mt][dn][2], o[mt][dn][3]);
            }
        }
    }
    __syncthreads();
    if (cs == 0) {
        #pragma unroll
        for (int mt = 0; mt < 2; mt++) {
            int r0 = rm * 32 + mt * 16 + grp, r1 = r0 + 8;
            float inv0 = 1.f / (sL[r0] + sL[128 + r0]);
            float inv1 = 1.f / (sL[r1] + sL[128 + r1]);
            __half* op0 = O + ((size_t)b * S_LEN + q0 + r0) * DM + hh * 64;
            __half* op1 = O + ((size_t)b * S_LEN + q0 + r1) * DM + hh * 64;
            #pragma unroll
            for (int dn = 0; dn < 8; dn++) {
                int c = dn * 8 + 2 * tig;
                float2 p0 = *(float2*)&stg[r0 * 64 + c];
                float2 p1 = *(float2*)&stg[r1 * 64 + c];
                *(__half2*)(op0 + c) = __floats2half2_rn(
                    (o[mt][dn][0] + p0.x) * inv0, (o[mt][dn][1] + p0.y) * inv0);
                *(__half2*)(op1 + c) = __floats2half2_rn(
                    (o[mt][dn][2] + p1.x) * inv1, (o[mt][dn][3] + p1.y) * inv1);
            }
        }
    }
}

// ===========================================================================
// prep kernels
// ===========================================================================
__global__ void cvt_x(const float4* __restrict__ src, uint2* __restrict__ dst) {
    int i = blockIdx.x * 256 + threadIdx.x;
    float4 v = src[i];
    uint2 u;
    u.x = h2u(__floats2half2_rn(v.x, v.y));
    u.y = h2u(__floats2half2_rn(v.z, v.w));
    dst[i] = u;
}

__global__ void transposeW(const float* __restrict__ s0, const float* __restrict__ s1,
                           const float* __restrict__ s2, const float* __restrict__ s3,
                           __half* __restrict__ dstAll) {
    __shared__ float t[32][33];
    const float* src = (blockIdx.z == 0) ? s0 : (blockIdx.z == 1) ? s1
                     : (blockIdx.z == 2) ? s2 : s3;
    __half* dst = dstAll + (size_t)blockIdx.z * DM * DM;
    int x0 = blockIdx.x * 32, y0 = blockIdx.y * 32;
    int tx = threadIdx.x, ty = threadIdx.y;
    #pragma unroll
    for (int i = 0; i < 4; i++)
        t[ty + i * 8][tx] = src[(size_t)(y0 + ty + i * 8) * 512 + x0 + tx];
    __syncthreads();
    #pragma unroll
    for (int i = 0; i < 4; i++)
        dst[(size_t)(x0 + ty + i * 8) * 512 + y0 + tx] =
            __float2half_rn(t[tx][ty + i * 8]);
}

__global__ void transpose_v(const __half* __restrict__ V, __half* __restrict__ Vt) {
    __shared__ __half t[32][33];
    int bh = blockIdx.z, b = bh >> 3, h = bh & 7;
    int s0 = blockIdx.x * 32, d0 = blockIdx.y * 32;
    int tx = threadIdx.x, ty = threadIdx.y;
    #pragma unroll
    for (int i = 0; i < 4; i++)
        t[ty + i * 8][tx] =
            V[((size_t)b * S_LEN + s0 + ty + i * 8) * DM + h * 64 + d0 + tx];
    __syncthreads();
    #pragma unroll
    for (int i = 0; i < 4; i++)
        Vt[((size_t)bh * 64 + d0 + ty + i * 8) * S_LEN + s0 + tx] = t[tx][ty + i * 8];
}

// ===========================================================================
extern "C" void kernel_launch(void* const* d_in, const int* in_sizes, int n_in,
                              void* d_out, int out_size)
{
    const float* x  = (const float*)d_in[0];
    const float* Wq = (const float*)d_in[1];
    const float* bq = (const float*)d_in[2];
    const float* Wk = (const float*)d_in[3];
    const float* bk = (const float*)d_in[4];
    const float* Wv = (const float*)d_in[5];
    const float* bv = (const float*)d_in[6];
    const float* Wh = (const float*)d_in[7];
    const float* bh = (const float*)d_in[8];
    float* out = (float*)d_out;

    __half *Xp, *Qp, *Kp, *Vp, *Vtp, *Ap, *Wtp;
    cudaGetSymbolAddress((void**)&Xp, g_Xh);
    cudaGetSymbolAddress((void**)&Qp, g_Q);
    cudaGetSymbolAddress((void**)&Kp, g_K);
    cudaGetSymbolAddress((void**)&Vp, g_V);
    cudaGetSymbolAddress((void**)&Vtp, g_Vt);
    cudaGetSymbolAddress((void**)&Ap, g_A);
    cudaGetSymbolAddress((void**)&Wtp, g_Wt);

    const int GEMM_SMEM = 61440;
    const int ATTN_SMEM = 126976;
    cudaFuncSetAttribute(gemm_mma, cudaFuncAttributeMaxDynamicSharedMemorySize, GEMM_SMEM);
    cudaFuncSetAttribute(attn_mma, cudaFuncAttributeMaxDynamicSharedMemorySize, ATTN_SMEM);

    cvt_x<<<MROWS * DM / 4 / 256, 256>>>((const float4*)x, (uint2*)Xp);

    dim3 tb(32, 8);
    transposeW<<<dim3(16, 16, 4), tb>>>(Wq, Wk, Wv, Wh, Wtp);

    dim3 ggrid(2, 64);   // 128 CTAs, one wave
    gemm_mma<<<ggrid, 256, GEMM_SMEM>>>(Xp, Wtp + 0 * DM * DM, bq, Qp, 1);
    gemm_mma<<<ggrid, 256, GEMM_SMEM>>>(Xp, Wtp + 1 * DM * DM, bk, Kp, 1);
    gemm_mma<<<ggrid, 256, GEMM_SMEM>>>(Xp, Wtp + 2 * DM * DM, bv, Vp, 1);

    transpose_v<<<dim3(64, 2, 32), tb>>>(Vp, Vtp);

    attn_mma<<<dim3(16, 32), 256, ATTN_SMEM>>>(Qp, Kp, Vtp, Ap);

    gemm_mma<<<ggrid, 256, GEMM_SMEM>>>(Ap, Wtp + 3 * DM * DM, bh, out, 0);
}